// round 11
// baseline (speedup 1.0000x reference)
#include <cuda_runtime.h>
#include <cstdint>

#define KCODES   512
#define DDIM     64
#define HWSZ     4096
#define NPTS     131072
#define TPTS     128            // points per tile
#define NTILES   (NPTS / TPTS)  // 1024
#define ZQ_ELEMS 8388608
#define NTHREADS 512

// ---- kernel1 SMEM (bytes) ----
//  s_cbd : u64[64ch][128code]  duplicated quarter codebook {e,e}   65536
//  s_z   : u64[64ch][64pp]     point-pair packed z {z2p, z2p+1}    32768
//  s_en  : f32[128]            quarter ||e||^2                     512
//  s_zn  : f32[128]            ||z||^2                             512
//  s_pm  : f32[4cg][128pt]     per-codegroup best dist             2048
//  s_pk  : i32[4cg][128pt]                                         2048
#define OFF_CBD  0
#define OFF_Z    65536
#define OFF_EN   98304
#define OFF_ZN   98816
#define OFF_PM   99328
#define OFF_PK   101376
#define SMEM_BYTES 103424

__device__ float g_dpart[4ull * NPTS];
__device__ int   g_kpart[4ull * NPTS];

__device__ __forceinline__ unsigned long long pk2(float lo, float hi) {
    unsigned long long r;
    asm("mov.b64 %0, {%1,%2};" : "=l"(r) : "f"(lo), "f"(hi));
    return r;
}
__device__ __forceinline__ float2 unpk2(unsigned long long v) {
    float2 f;
    asm("mov.b64 {%0,%1}, %2;" : "=f"(f.x), "=f"(f.y) : "l"(v));
    return f;
}
// packed dual-fp32 FMA (sm_100+; PTX-only) — two independent rn fmas
__device__ __forceinline__ void ffma2(unsigned long long& d,
                                      unsigned long long a,
                                      unsigned long long b) {
    asm("fma.rn.f32x2 %0, %1, %2, %0;" : "+l"(d) : "l"(a), "l"(b));
}

// ---- kernel 1: per-quarter sweep, partials to gmem ----
__global__ void __launch_bounds__(NTHREADS, 2)
vq_sweep(const float* __restrict__ z_e,
         const float* __restrict__ cb,
         int nctas)
{
    extern __shared__ char smem[];
    unsigned long long* s_cbd = (unsigned long long*)(smem + OFF_CBD);
    unsigned long long* s_z   = (unsigned long long*)(smem + OFF_Z);
    float* s_en = (float*)(smem + OFF_EN);
    float* s_zn = (float*)(smem + OFF_ZN);
    float* s_pm = (float*)(smem + OFF_PM);
    int*   s_pk = (int*)  (smem + OFF_PK);

    const int tid   = threadIdx.x;
    const int lane  = tid & 31;
    const int w     = tid >> 5;
    const int ppg   = w & 3;          // pt-pair group: pairs [ppg*16, +16)
    const int cg    = w >> 2;         // code group: local codes [cg*32, +32)
    const int ppart = lane & 3;       // 4 pt-pairs: ppg*16 + ppart*4 ..+4
    const int cpart = lane >> 2;      // 4 codes:    cg*32 + cpart*4 ..+4
    const int ppb   = ppg * 16 + ppart * 4;
    const int clb   = cg * 32 + cpart * 4;

    const int q     = blockIdx.x & 3;             // code quarter
    const int step  = nctas >> 2;

    // ---- Stage quarter codebook once: dup {e,e} + exact fp32 norms ----
    {
        // dup: 512 threads, code = tid&127, channels [(tid>>7)*16, +16)
        const int code = tid & 127;
        const int c0   = (tid >> 7) * 16;
        const float4* e4 = (const float4*)(cb + (size_t)(q * 128 + code) * DDIM + c0);
        #pragma unroll
        for (int c4 = 0; c4 < 4; c4++) {
            float4 a = e4[c4];
            int c = c0 + 4 * c4;
            s_cbd[(c+0) * 128 + code] = pk2(a.x, a.x);
            s_cbd[(c+1) * 128 + code] = pk2(a.y, a.y);
            s_cbd[(c+2) * 128 + code] = pk2(a.z, a.z);
            s_cbd[(c+3) * 128 + code] = pk2(a.w, a.w);
        }
        if (tid < 128) {   // exact norm, same chain as proven kernels
            const float4* e0 = (const float4*)(cb + (size_t)(q * 128 + tid) * DDIM);
            float nrm = 0.f;
            #pragma unroll
            for (int c4 = 0; c4 < 16; c4++) {
                float4 a = e0[c4];
                nrm += a.x*a.x + a.y*a.y + a.z*a.z + a.w*a.w;
            }
            s_en[tid] = nrm;
        }
    }

    for (int tile = blockIdx.x >> 2; tile < NTILES; tile += step) {
        __syncthreads();     // s_z / s_pm free

        // ---- Stage z tile, point-pair packed ----
        {
            const float* zg = z_e + (size_t)(tile >> 5) * (DDIM * HWSZ)
                                  + (size_t)(tile & 31) * TPTS;
            #pragma unroll
            for (int it = 0; it < 4; it++) {
                int i4 = it * NTHREADS + tid;   // 0..2047 float4 slots
                int c  = i4 >> 5;
                int p4 = (i4 & 31) * 4;
                float4 v = *(const float4*)(zg + (size_t)c * HWSZ + p4);
                *(ulonglong2*)(s_z + c * 64 + (p4 >> 1)) =
                    make_ulonglong2(pk2(v.x, v.y), pk2(v.z, v.w));
            }
        }
        __syncthreads();

        // ---- znorm per point (exact channel-sequential chain) ----
        if (tid < 128) {
            const float* zc = (const float*)s_z;
            float zn = 0.f;
            #pragma unroll 8
            for (int c = 0; c < 64; c++) {
                float v = zc[(c * 64 + (tid >> 1)) * 2 + (tid & 1)];
                zn = fmaf(v, v, zn);
            }
            s_zn[tid] = zn;
        }
        __syncthreads();

        // ---- Sweep: 4 pt-pairs x 4 codes per thread over 64 channels ----
        unsigned long long acc[4][4];
        #pragma unroll
        for (int m = 0; m < 4; m++)
            #pragma unroll
            for (int j = 0; j < 4; j++) acc[m][j] = 0ull;

        {
            const unsigned long long* pz = s_z + ppb;
            const unsigned long long* pc = s_cbd + clb;
            #pragma unroll 8
            for (int c = 0; c < 64; c++) {
                ulonglong2 za = ((const ulonglong2*)pz)[0];
                ulonglong2 zb = ((const ulonglong2*)pz)[1];
                ulonglong2 ca = ((const ulonglong2*)pc)[0];
                ulonglong2 cbv = ((const ulonglong2*)pc)[1];
                unsigned long long zr[4] = { za.x, za.y, zb.x, zb.y };
                unsigned long long cr[4] = { ca.x, ca.y, cbv.x, cbv.y };
                #pragma unroll
                for (int m = 0; m < 4; m++)
                    #pragma unroll
                    for (int j = 0; j < 4; j++)
                        ffma2(acc[m][j], zr[m], cr[j]);
                pz += 64;
                pc += 128;
            }
        }

        // ---- Per-thread argmin (8 points, ascending code order) ----
        float bestD[8]; int bestK[8];
        #pragma unroll
        for (int m = 0; m < 8; m++) { bestD[m] = 3.402823e38f; bestK[m] = 0; }
        float znm[8];
        #pragma unroll
        for (int m = 0; m < 8; m++) znm[m] = s_zn[ppb * 2 + m];

        #pragma unroll
        for (int j = 0; j < 4; j++) {
            float en = s_en[clb + j];
            int k = q * 128 + clb + j;          // global code
            #pragma unroll
            for (int m = 0; m < 4; m++) {
                float2 d = unpk2(acc[m][j]);
                float dd = znm[2*m] + en - 2.f * d.x;
                if (dd < bestD[2*m])   { bestD[2*m]   = dd; bestK[2*m]   = k; }
                dd = znm[2*m+1] + en - 2.f * d.y;
                if (dd < bestD[2*m+1]) { bestD[2*m+1] = dd; bestK[2*m+1] = k; }
            }
        }

        // ---- Reduce across cpart (xor 4,8,16; ppart fixed; tie -> lower k) ----
        #pragma unroll
        for (int m = 0; m < 8; m++) {
            float d = bestD[m]; int k = bestK[m];
            #pragma unroll
            for (int s = 4; s < 32; s <<= 1) {
                float od = __shfl_xor_sync(0xFFFFFFFFu, d, s);
                int   ok = __shfl_xor_sync(0xFFFFFFFFu, k, s);
                if (od < d || (od == d && ok < k)) { d = od; k = ok; }
            }
            if (cpart == 0) {
                s_pm[cg * 128 + ppb * 2 + m] = d;
                s_pk[cg * 128 + ppb * 2 + m] = k;
            }
        }
        __syncthreads();

        // ---- Merge 4 code groups (ascending k), write quarter partial ----
        if (tid < 128) {
            float d = s_pm[tid]; int k = s_pk[tid];
            #pragma unroll
            for (int g2 = 1; g2 < 4; g2++) {
                float od = s_pm[g2 * 128 + tid]; int ok = s_pk[g2 * 128 + tid];
                if (od < d || (od == d && ok < k)) { d = od; k = ok; }
            }
            g_dpart[(size_t)q * NPTS + tile * 128 + tid] = d;
            g_kpart[(size_t)q * NPTS + tile * 128 + tid] = k;
        }
    }
}

// ---- kernel 2: merge quarters + emit ----
__global__ void __launch_bounds__(256, 4)
vq_merge(const float* __restrict__ cb,
         float* __restrict__ out,
         int mode)
{
    __shared__ int s_idx[128];
    const int tile = blockIdx.x;
    const int tid  = threadIdx.x;

    if (tid < 128) {
        int n = tile * 128 + tid;
        float d = g_dpart[n]; int k = g_kpart[n];
        #pragma unroll
        for (int q = 1; q < 4; q++) {
            float od = g_dpart[(size_t)q * NPTS + n];
            int   ok = g_kpart[(size_t)q * NPTS + n];
            if (od < d || (od == d && ok < k)) { d = od; k = ok; }
        }
        s_idx[tid] = k;
    }
    __syncthreads();

    if (mode == 2) {
        if (tid < 128) ((int*)out)[tile * 128 + tid] = s_idx[tid];
    } else {
        float4* out4 = (float4*)out + (size_t)tile * 2048;
        const float4* cb4 = (const float4*)cb;
        #pragma unroll
        for (int it = 0; it < 8; it++) {
            int i4 = it * 256 + tid;
            int p  = i4 >> 4;
            int c4 = i4 & 15;
            out4[i4] = cb4[(size_t)s_idx[p] * 16 + c4];
        }
        if (mode == 1 && tid < 128)
            out[ZQ_ELEMS + tile * 128 + tid] = (float)s_idx[tid];
    }
}

extern "C" void kernel_launch(void* const* d_in, const int* in_sizes, int n_in,
                              void* d_out, int out_size)
{
    const float* z_e = (const float*)d_in[0];
    const float* cb  = (const float*)d_in[1];
    float* out = (float*)d_out;

    int mode;
    if (out_size >= ZQ_ELEMS + NPTS) mode = 1;
    else if (out_size >= ZQ_ELEMS)   mode = 0;
    else                             mode = 2;

    int sms = 0;
    cudaDeviceGetAttribute(&sms, cudaDevAttrMultiProcessorCount, 0);
    if (sms <= 0) sms = 148;
    int nctas = (2 * sms) & ~3;       // divisible by 4 (one quarter per bid&3)

    cudaFuncSetAttribute(vq_sweep, cudaFuncAttributeMaxDynamicSharedMemorySize, SMEM_BYTES);
    vq_sweep<<<nctas, NTHREADS, SMEM_BYTES>>>(z_e, cb, nctas);
    vq_merge<<<NTILES, 256>>>(cb, out, mode);
}

// round 12
// speedup vs baseline: 1.5090x; 1.5090x over previous
#include <cuda_runtime.h>
#include <cuda_bf16.h>
#include <cstdint>

#define KCODES   512
#define DDIM     64
#define HWSZ     4096
#define NPTS     131072
#define TPTS     128
#define NTILES   1024
#define ZQ_ELEMS 8388608
#define NTHREADS 256

#define STRZ     65           // floats per z row (pad -> conflict-free)

// ---- SMEM layout (bytes) ----
// cb frag-major: [64 nblk][4 j][32 lane][8B] = 65536
#define OFF_CB   0
#define OFF_ZF   65536                     // f32 z [128][65]            = 33280
#define OFF_EN   98816                     // f32 ||e||^2 [512]          = 2048
#define OFF_ZN   100864                    // f32 ||z||^2 [128]          = 512
#define OFF_THR  101376                    // f32 thr [128]              = 512
#define OFF_PM   101888                    // f32 per-row min [128]      = 512
#define OFF_KEY  102400                    // u64 best key [128]         = 1024
#define OFF_IDX  103424                    // i32 idx [128]              = 512
#define OFF_EMX  103936                    // i32 emax bits              = 16
#define SMEM_BYTES 103952

__device__ __forceinline__ void mma16816(float* d, const uint32_t* a,
                                         uint32_t b0, uint32_t b1) {
    asm volatile("mma.sync.aligned.m16n8k16.row.col.f32.bf16.bf16.f32 "
                 "{%0,%1,%2,%3}, {%4,%5,%6,%7}, {%8,%9}, {%0,%1,%2,%3};"
                 : "+f"(d[0]), "+f"(d[1]), "+f"(d[2]), "+f"(d[3])
                 : "r"(a[0]), "r"(a[1]), "r"(a[2]), "r"(a[3]), "r"(b0), "r"(b1));
}
__device__ __forceinline__ uint32_t packbf(float lo, float hi) {
    uint32_t r;
    asm("cvt.rn.bf16x2.f32 %0, %1, %2;" : "=r"(r) : "f"(hi), "f"(lo));
    return r;
}

// exact fp32 rescore: channel-sequential fma chain (same order as proven kernels)
__device__ __forceinline__ void rescore(const float* zf, const float* s_zn,
                                        const float* s_en, unsigned long long* s_key,
                                        const float* cb, int p, int k) {
    const float* er = cb + (size_t)k * DDIM;
    const float* zp = zf + p * STRZ;
    float dot = 0.f;
    #pragma unroll 8
    for (int c = 0; c < DDIM; c++) dot = fmaf(zp[c], __ldg(er + c), dot);
    float dd = s_zn[p] + s_en[k] - 2.f * dot;
    unsigned long long key = ((unsigned long long)__float_as_uint(dd) << 32) | (unsigned)k;
    atomicMin(&s_key[p], key);
}

// 8-code-block batch: 16 rows x 64 cols, K=64. Frag-major LDS.64: coalesced,
// conflict-free, addresses (Bblk*4 + j)*256 + lane*8.
__device__ __forceinline__ void run_mma8(float acc[8][4], const uint32_t ra[4][4],
                                         const char* cbb, int Bbase, int lane) {
    #pragma unroll
    for (int f = 0; f < 8; f++)
        #pragma unroll
        for (int e = 0; e < 4; e++) acc[f][e] = 0.f;
    const char* base = cbb + (size_t)Bbase * 1024 + lane * 8;
    #pragma unroll
    for (int j = 0; j < 4; j++) {
        #pragma unroll
        for (int f = 0; f < 8; f++) {
            uint2 bb = *(const uint2*)(base + f * 1024 + j * 256);
            mma16816(acc[f], ra[j], bb.x, bb.y);
        }
    }
}

// mode: 0 = z_q only; 1 = z_q + indices-as-float appended; 2 = indices only
__global__ void __launch_bounds__(NTHREADS, 2)
vq_kernel(const float* __restrict__ z_e,
          const float* __restrict__ cb,
          float* __restrict__ out,
          int mode, int nctas)
{
    extern __shared__ char smem[];
    float* zf    = (float*)(smem + OFF_ZF);
    float* s_en  = (float*)(smem + OFF_EN);
    float* s_zn  = (float*)(smem + OFF_ZN);
    float* s_thr = (float*)(smem + OFF_THR);
    float* s_pm  = (float*)(smem + OFF_PM);
    unsigned long long* s_key = (unsigned long long*)(smem + OFF_KEY);
    int*   s_idx = (int*)(smem + OFF_IDX);
    int*   s_emx = (int*)(smem + OFF_EMX);

    const int tid  = threadIdx.x;
    const int w    = tid >> 5;           // 8 warps
    const int lane = tid & 31;
    const int g    = lane >> 2;
    const int tig  = lane & 3;
    const int m0   = w * 16;             // warp's 16 rows; all 512 codes

    if (tid == 0) *s_emx = 0;
    __syncthreads();

    // ---- Stage codebook once: frag-major bf16 + fp32 ||e||^2 + emax ----
    // code k -> nblk k>>3, col k&7; within 8B: h*4+b*2 <- c = j*16+2*tig+b+8*h
    for (int k = tid; k < KCODES; k += NTHREADS) {
        const float4* e4 = (const float4*)(cb + (size_t)k * DDIM);
        char* base = smem + OFF_CB + (size_t)(k >> 3) * 1024 + (k & 7) * 32;
        float nrm = 0.f, amx = 0.f;
        #pragma unroll
        for (int c4 = 0; c4 < 16; c4++) {
            float4 a = e4[c4];
            float vv[4] = { a.x, a.y, a.z, a.w };
            #pragma unroll
            for (int q = 0; q < 4; q++) {
                int c = 4 * c4 + q;
                float v = vv[q];
                nrm = fmaf(v, v, nrm);
                amx = fmaxf(amx, fabsf(v));
                int j = c >> 4, kk = c & 15;
                int tg = (kk & 7) >> 1, h = kk >> 3, b = kk & 1;
                *(__nv_bfloat16*)(base + j * 256 + tg * 8 + h * 4 + b * 2) =
                    __float2bfloat16(v);
            }
        }
        s_en[k] = nrm;
        atomicMax(s_emx, __float_as_int(amx));
    }
    __syncthreads();
    const float emax = __int_as_float(*s_emx);

    for (int tile = blockIdx.x; tile < NTILES; tile += nctas) {
        __syncthreads();   // prior tile's consumers of zf/s_key done

        // ---- Stage z tile fp32 -> zf[p][c] (padded) ----
        {
            const float* zg = z_e + (size_t)(tile >> 5) * (DDIM * HWSZ)
                                  + (size_t)(tile & 31) * TPTS;
            #pragma unroll
            for (int it = 0; it < 8; it++) {
                int i4 = it * NTHREADS + tid;          // 0..2047
                int c = i4 >> 5, p = (i4 & 31) * 4;
                float4 v = *(const float4*)(zg + (size_t)c * HWSZ + p);
                zf[(p + 0) * STRZ + c] = v.x;
                zf[(p + 1) * STRZ + c] = v.y;
                zf[(p + 2) * STRZ + c] = v.z;
                zf[(p + 3) * STRZ + c] = v.w;
            }
        }
        __syncthreads();

        // ---- znorm + sum|z| per point (exact-order fma chains) ----
        float sab = 0.f;
        if (tid < 128) {
            const float* zp = zf + tid * STRZ;
            float zn = 0.f;
            #pragma unroll 8
            for (int c = 0; c < DDIM; c++) {
                float v = zp[c];
                zn = fmaf(v, v, zn);
                sab += fabsf(v);
            }
            s_zn[tid] = zn;
        }

        // ---- Register A-fragments (bf16) for this warp's 16 rows ----
        uint32_t ra[4][4];
        #pragma unroll
        for (int j = 0; j < 4; j++) {
            const float* r0 = zf + (m0 + g) * STRZ + 16 * j + 2 * tig;
            const float* r1 = zf + (m0 + g + 8) * STRZ + 16 * j + 2 * tig;
            ra[j][0] = packbf(r0[0], r0[1]);
            ra[j][1] = packbf(r1[0], r1[1]);
            ra[j][2] = packbf(r0[8], r0[9]);
            ra[j][3] = packbf(r1[8], r1[9]);
        }

        // ---- Pass 1: all 64 code blocks in batches of 8; fold row mins ----
        float rm0 = 3.402823e38f, rm1 = 3.402823e38f;
        for (int nb = 0; nb < 8; nb++) {
            float acc[8][4];
            run_mma8(acc, ra, smem + OFF_CB, nb * 8, lane);
            #pragma unroll
            for (int f = 0; f < 8; f++) {
                int k0 = (nb * 8 + f) * 8 + 2 * tig;
                float e0 = s_en[k0], e1 = s_en[k0 + 1];
                rm0 = fminf(rm0, fminf(e0 - 2.f * acc[f][0], e1 - 2.f * acc[f][1]));
                rm1 = fminf(rm1, fminf(e0 - 2.f * acc[f][2], e1 - 2.f * acc[f][3]));
            }
        }
        rm0 = fminf(rm0, __shfl_xor_sync(0xFFFFFFFFu, rm0, 1));
        rm0 = fminf(rm0, __shfl_xor_sync(0xFFFFFFFFu, rm0, 2));
        rm1 = fminf(rm1, __shfl_xor_sync(0xFFFFFFFFu, rm1, 1));
        rm1 = fminf(rm1, __shfl_xor_sync(0xFFFFFFFFu, rm1, 2));
        if (tig == 0) {
            s_pm[m0 + g]     = rm0;
            s_pm[m0 + g + 8] = rm1;
        }
        __syncthreads();

        // ---- Threshold: guaranteed window around approx min ----
        if (tid < 128) {
            float S = sab * emax;                 // >= sum |z_c||e_c|
            s_thr[tid] = s_pm[tid] + fmaf(0.018f, S, 1.5e-4f);   // 2B with margin
            s_key[tid] = ~0ull;
        }
        __syncthreads();

        // ---- Pass 2: recompute, collect per-lane candidates, exact rescore ----
        {
            const float thrA = s_thr[m0 + g];
            const float thrB = s_thr[m0 + g + 8];
            const int pA = m0 + g, pB = m0 + g + 8;
            uint32_t cl[4]; int cnt = 0;
            for (int nb = 0; nb < 8; nb++) {
                float acc[8][4];
                run_mma8(acc, ra, smem + OFF_CB, nb * 8, lane);
                #pragma unroll
                for (int f = 0; f < 8; f++) {
                    int k0 = (nb * 8 + f) * 8 + 2 * tig;
                    float e0 = s_en[k0], e1 = s_en[k0 + 1];
                    float t00 = e0 - 2.f * acc[f][0];
                    float t01 = e1 - 2.f * acc[f][1];
                    float t10 = e0 - 2.f * acc[f][2];
                    float t11 = e1 - 2.f * acc[f][3];
                    #pragma unroll
                    for (int e = 0; e < 4; e++) {
                        bool cond; int p, kk;
                        if (e == 0)      { cond = (t00 <= thrA); p = pA; kk = k0;     }
                        else if (e == 1) { cond = (t01 <= thrA); p = pA; kk = k0 + 1; }
                        else if (e == 2) { cond = (t10 <= thrB); p = pB; kk = k0;     }
                        else             { cond = (t11 <= thrB); p = pB; kk = k0 + 1; }
                        if (cond) {
                            if (cnt < 4) cl[cnt] = ((unsigned)p << 9) | (unsigned)kk;
                            else rescore(zf, s_zn, s_en, s_key, cb, p, kk);
                            cnt++;
                        }
                    }
                }
            }
            int nn = cnt < 4 ? cnt : 4;
            for (int i = 0; i < nn; i++)
                rescore(zf, s_zn, s_en, s_key, cb, (int)(cl[i] >> 9), (int)(cl[i] & 511));
        }
        __syncthreads();

        if (tid < 128) s_idx[tid] = (int)(s_key[tid] & 0xFFFFFFFFull);
        __syncthreads();

        // ---- Emit ----
        if (mode == 2) {
            if (tid < 128) ((int*)out)[tile * 128 + tid] = s_idx[tid];
        } else {
            float4* out4 = (float4*)out + (size_t)tile * 2048;
            const float4* cb4 = (const float4*)cb;
            #pragma unroll
            for (int it = 0; it < 8; it++) {
                int i4 = it * NTHREADS + tid;
                int p = i4 >> 4, c4 = i4 & 15;
                out4[i4] = cb4[(size_t)s_idx[p] * 16 + c4];
            }
            if (mode == 1 && tid < 128)
                out[ZQ_ELEMS + tile * 128 + tid] = (float)s_idx[tid];
        }
    }
}

extern "C" void kernel_launch(void* const* d_in, const int* in_sizes, int n_in,
                              void* d_out, int out_size)
{
    const float* z_e = (const float*)d_in[0];
    const float* cb  = (const float*)d_in[1];
    float* out = (float*)d_out;

    int mode;
    if (out_size >= ZQ_ELEMS + NPTS) mode = 1;
    else if (out_size >= ZQ_ELEMS)   mode = 0;
    else                             mode = 2;

    int sms = 0;
    cudaDeviceGetAttribute(&sms, cudaDevAttrMultiProcessorCount, 0);
    if (sms <= 0) sms = 148;
    int nctas = 2 * sms;

    cudaFuncSetAttribute(vq_kernel, cudaFuncAttributeMaxDynamicSharedMemorySize, SMEM_BYTES);
    vq_kernel<<<nctas, NTHREADS, SMEM_BYTES>>>(z_e, cb, out, mode, nctas);
}